// round 9
// baseline (speedup 1.0000x reference)
#include <cuda_runtime.h>
#include <cstdint>

// Problem constants
#define BB   128   // batch
#define INW  256   // input width
#define HH   1024  // hidden
#define NP   512   // pairs per A layer
#define LP   128   // number of (A,B) layer pairs (L=256 layers total)
#define FULLMASK 0xffffffffu

// Transposed trig tables: [layer][j][thread] so lane stride is 16B (coalesced).
// j in {0,1}: A-layer pair 2t+j; B: j=0 -> middle pair 2t, j=1 -> edge pair 2t+1.
// Padded +2 layers so depth-2 prefetch never faults.
__device__ float4 g_tA[LP + 2][2][256];
__device__ float4 g_tB[LP + 2][2][256];
__device__ float  g_pR[4][BB * HH];         // GEMM partials per K-chunk
__device__ float  g_pI[4][BB * HH];

// ---------------------------------------------------------------------------
// Kernel 1: blocks [0,128) = complex GEMM (K-split x4, N-tiles of 32)
//           blocks [128,256) = trig table build (one block per layer pair)
// ---------------------------------------------------------------------------
__global__ __launch_bounds__(256) void k1(
    const float* __restrict__ inR, const float* __restrict__ inI,
    const float* __restrict__ wR,  const float* __restrict__ wI,
    const float* __restrict__ A0,  const float* __restrict__ A1,
    const float* __restrict__ B0,  const float* __restrict__ B1)
{
    const int bid = blockIdx.x, tid = threadIdx.x;

    if (bid >= 128) {
        const int k = bid - 128;
        for (int idx = tid; idx < NP; idx += 256) {
            float c0, s0, c1, s1;
            sincosf(A0[k * NP + idx], &s0, &c0);
            sincosf(A1[k * NP + idx], &s1, &c1);
            g_tA[k][idx & 1][idx >> 1] = make_float4(c0, s0, c1, s1);
        }
        for (int idx = tid; idx < NP; idx += 256) {
            float ang0 = (idx < NP - 1) ? B0[k * (NP - 1) + idx] : 0.f;
            float ang1 = (idx < NP - 1) ? B1[k * (NP - 1) + idx] : 0.f;
            float c0, s0, c1, s1;
            sincosf(ang0, &s0, &c0);
            sincosf(ang1, &s1, &c1);
            g_tB[k][idx & 1][idx >> 1] = make_float4(c0, s0, c1, s1);
        }
        return;
    }

    // ---- complex GEMM: tile M=128, N=32, K-chunk=64 ----
    const int kc = bid >> 5, nt = bid & 31;
    const int k0 = kc * 64, n0 = nt * 32;

    __shared__ float sXR[32][132], sXI[32][132];
    __shared__ float sWR[32][33],  sWI[32][33];

    float accR[8][2], accI[8][2];
    #pragma unroll
    for (int r = 0; r < 8; r++)
        #pragma unroll
        for (int c = 0; c < 2; c++) { accR[r][c] = 0.f; accI[r][c] = 0.f; }

    const int mi = tid >> 4, ni = tid & 15;
    const int lm = tid & 127, kh = (tid >> 7) * 16;
    const int wn = tid >> 3,  wk = (tid & 7) * 4;

    for (int ks = 0; ks < 64; ks += 32) {
        __syncthreads();
        #pragma unroll
        for (int j = 0; j < 4; j++) {
            const int kk = kh + j * 4;
            float4 vR = *(const float4*)(inR + lm * INW + k0 + ks + kk);
            float4 vI = *(const float4*)(inI + lm * INW + k0 + ks + kk);
            sXR[kk+0][lm] = vR.x; sXR[kk+1][lm] = vR.y;
            sXR[kk+2][lm] = vR.z; sXR[kk+3][lm] = vR.w;
            sXI[kk+0][lm] = vI.x; sXI[kk+1][lm] = vI.y;
            sXI[kk+2][lm] = vI.z; sXI[kk+3][lm] = vI.w;
        }
        {
            float4 vR = *(const float4*)(wR + (n0 + wn) * INW + k0 + ks + wk);
            float4 vI = *(const float4*)(wI + (n0 + wn) * INW + k0 + ks + wk);
            sWR[wk+0][wn] = vR.x; sWR[wk+1][wn] = vR.y;
            sWR[wk+2][wn] = vR.z; sWR[wk+3][wn] = vR.w;
            sWI[wk+0][wn] = vI.x; sWI[wk+1][wn] = vI.y;
            sWI[wk+2][wn] = vI.z; sWI[wk+3][wn] = vI.w;
        }
        __syncthreads();

        #pragma unroll 8
        for (int kk = 0; kk < 32; kk++) {
            float aRv[8], aIv[8], bRv[2], bIv[2];
            *(float4*)&aRv[0] = *(const float4*)&sXR[kk][mi * 8];
            *(float4*)&aRv[4] = *(const float4*)&sXR[kk][mi * 8 + 4];
            *(float4*)&aIv[0] = *(const float4*)&sXI[kk][mi * 8];
            *(float4*)&aIv[4] = *(const float4*)&sXI[kk][mi * 8 + 4];
            bRv[0] = sWR[kk][ni*2]; bRv[1] = sWR[kk][ni*2+1];
            bIv[0] = sWI[kk][ni*2]; bIv[1] = sWI[kk][ni*2+1];
            #pragma unroll
            for (int r = 0; r < 8; r++)
                #pragma unroll
                for (int c = 0; c < 2; c++) {
                    accR[r][c] += aRv[r]*bRv[c] - aIv[r]*bIv[c];
                    accI[r][c] += aRv[r]*bIv[c] + aIv[r]*bRv[c];
                }
        }
    }

    #pragma unroll
    for (int r = 0; r < 8; r++) {
        const int m = mi * 8 + r;
        #pragma unroll
        for (int c = 0; c < 2; c++) {
            g_pR[kc][m * HH + n0 + ni*2 + c] = accR[r][c];
            g_pI[kc][m * HH + n0 + ni*2 + c] = accI[r][c];
        }
    }
}

// ---------------------------------------------------------------------------
// helpers
// ---------------------------------------------------------------------------
__device__ __forceinline__ float4 ldg_v4_pinned(const float4* p) {
    float4 v;
    asm volatile("ld.global.nc.v4.f32 {%0,%1,%2,%3}, [%4];"
                 : "=f"(v.x), "=f"(v.y), "=f"(v.z), "=f"(v.w) : "l"(p));
    return v;
}

__device__ __forceinline__ void pub_pred(uint32_t addr, int pred,
                                         float x, float y, float z) {
    asm volatile("{\n\t"
                 ".reg .pred p;\n\t"
                 "setp.ne.s32 p, %0, 0;\n\t"
                 "@p st.shared.v4.f32 [%1], {%2,%3,%4,%2};\n\t"
                 "}"
                 :: "r"(pred), "r"(addr), "f"(x), "f"(y), "f"(z)
                 : "memory");
}

__device__ __forceinline__ float4 lds4(uint32_t addr) {
    float4 v;
    asm volatile("ld.shared.v4.f32 {%0,%1,%2,%3}, [%4];"
                 : "=f"(v.x), "=f"(v.y), "=f"(v.z), "=f"(v.w) : "r"(addr)
                 : "memory");
    return v;
}

// ---------------------------------------------------------------------------
// Kernel 2: Clements mesh — 256 threads, 4 channels/thread, TWO batch rows
// per CTA (rows b and b+64). The per-iteration latency chain (shfl/LDS/bar)
// is amortized over 2 rows; trig LDG traffic per row halves.
// ---------------------------------------------------------------------------
__global__ __launch_bounds__(256, 1) void k2(
    const float* __restrict__ stR, const float* __restrict__ stI,
    const float* __restrict__ bR,  const float* __restrict__ bI,
    const float* __restrict__ om,  const float* __restrict__ mb,
    float* __restrict__ out)
{
    const int b0v = blockIdx.x, b1v = blockIdx.x + 64;
    const int t = threadIdx.x;
    const int w = t >> 5, l = t & 31;

    __shared__ float4 slotA[2][2][8];   // [row][parity][boundary]
    __shared__ float4 slotU[2][2][8];

    // thread t owns channels 4t..4t+3 of both rows
    float4 xr0 = ((const float4*)(stR + b0v * HH))[t];
    float4 xi0 = ((const float4*)(stI + b0v * HH))[t];
    float4 xr1 = ((const float4*)(stR + b1v * HH))[t];
    float4 xi1 = ((const float4*)(stI + b1v * HH))[t];
    float p0r = xr0.x, q0r = xr0.y, r0r = xr0.z, s0r = xr0.w;
    float p0i = xi0.x, q0i = xi0.y, r0i = xi0.z, s0i = xi0.w;
    float p1r = xr1.x, q1r = xr1.y, r1r = xr1.z, s1r = xr1.w;
    float p1i = xi1.x, q1i = xi1.y, r1i = xi1.z, s1i = xi1.w;

    const uint32_t baseA0 = (uint32_t)__cvta_generic_to_shared(&slotA[0][0][0]);
    const uint32_t baseA1 = (uint32_t)__cvta_generic_to_shared(&slotA[1][0][0]);
    const uint32_t baseU0 = (uint32_t)__cvta_generic_to_shared(&slotU[0][0][0]);
    const uint32_t baseU1 = (uint32_t)__cvta_generic_to_shared(&slotU[1][0][0]);
    const uint32_t sPubA = (uint32_t)(((w > 0) ? (w - 1) : 0) * 16);
    const uint32_t sPubU = (uint32_t)(w * 16);
    const uint32_t sRdA  = (uint32_t)(((w < 7) ? w : 6) * 16);
    const uint32_t sRdU  = (uint32_t)(((w > 0) ? (w - 1) : 0) * 16);
    const int isL0 = (l == 0), isL31 = (l == 31), isT0 = (t == 0);
    const int pubA = isL0 && (w > 0);
    const int pubU = isL31 && (w < 7);

    // coalesced trig streams: lane stride 16B, layer stride 512 float4
    const float4* pA0 = &g_tA[0][0][t];
    const float4* pA1 = &g_tA[0][1][t];
    const float4* pB0 = &g_tB[0][0][t];
    const float4* pB1 = &g_tB[0][1][t];

    float4 a0A = ldg_v4_pinned(pA0),        a1A = ldg_v4_pinned(pA1);
    float4 b0A = ldg_v4_pinned(pB0),        b1A = ldg_v4_pinned(pB1);
    float4 a0B = ldg_v4_pinned(pA0 + 512),  a1B = ldg_v4_pinned(pA1 + 512);
    float4 b0B = ldg_v4_pinned(pB0 + 512),  b1B = ldg_v4_pinned(pB1 + 512);

    #pragma unroll 2
    for (int k = 0; k < LP; k++) {
        const uint32_t boff = (uint32_t)((k & 1) << 7);   // parity * 8 slots * 16B

        float4 tA0 = a0A, tA1 = a1A, tB0 = b0A, tB1 = b1A;
        a0A = a0B; a1A = a1B; b0A = b0B; b1A = b1B;
        const int off = (k + 2) * 512;
        a0B = ldg_v4_pinned(pA0 + off);
        a1B = ldg_v4_pinned(pA1 + off);
        b0B = ldg_v4_pinned(pB0 + off);
        b1B = ldg_v4_pinned(pB1 + off);

        // ---- layer A, MZI (c0,c1) — both rows ----
        {
            float pr = tA0.x*p0r - tA0.y*p0i;
            float pi = tA0.y*p0r + tA0.x*p0i;
            float n0r = tA0.z*pr  - tA0.w*q0i;
            float n0i = tA0.z*pi  + tA0.w*q0r;
            float n1r = tA0.z*q0r - tA0.w*pi;
            float n1i = tA0.z*q0i + tA0.w*pr;
            p0r = n0r; p0i = n0i; q0r = n1r; q0i = n1i;
        }
        {
            float pr = tA0.x*p1r - tA0.y*p1i;
            float pi = tA0.y*p1r + tA0.x*p1i;
            float n0r = tA0.z*pr  - tA0.w*q1i;
            float n0i = tA0.z*pi  + tA0.w*q1r;
            float n1r = tA0.z*q1r - tA0.w*pi;
            float n1i = tA0.z*q1i + tA0.w*pr;
            p1r = n0r; p1i = n0i; q1r = n1r; q1i = n1i;
        }
        // early publish: lane0's post-A c0 crosses the left boundary (both rows)
        pub_pred(baseA0 + boff + sPubA, pubA, p0r, p0i, 0.f);
        pub_pred(baseA1 + boff + sPubA, pubA, p1r, p1i, 0.f);

        // ---- layer A, MZI (c2,c3) — both rows ----
        {
            float pr = tA1.x*r0r - tA1.y*r0i;
            float pi = tA1.y*r0r + tA1.x*r0i;
            float n2r = tA1.z*pr  - tA1.w*s0i;
            float n2i = tA1.z*pi  + tA1.w*s0r;
            float n3r = tA1.z*s0r - tA1.w*pi;
            float n3i = tA1.z*s0i + tA1.w*pr;
            r0r = n2r; r0i = n2i; s0r = n3r; s0i = n3i;
        }
        {
            float pr = tA1.x*r1r - tA1.y*r1i;
            float pi = tA1.y*r1r + tA1.x*r1i;
            float n2r = tA1.z*pr  - tA1.w*s1i;
            float n2i = tA1.z*pi  + tA1.w*s1r;
            float n3r = tA1.z*s1r - tA1.w*pi;
            float n3i = tA1.z*s1i + tA1.w*pr;
            r1r = n2r; r1i = n2i; s1r = n3r; s1i = n3i;
        }

        // ---- edge B MZI (c3, next c0): phase + u, publish right (both rows) ----
        float e0r = tB1.x*s0r - tB1.y*s0i;
        float e0i = tB1.y*s0r + tB1.x*s0i;
        float u0x = tB1.w*e0r, u0y = tB1.w*e0i, uz = tB1.z;
        float e1r = tB1.x*s1r - tB1.y*s1i;
        float e1i = tB1.y*s1r + tB1.x*s1i;
        float u1x = tB1.w*e1r, u1y = tB1.w*e1i;
        pub_pred(baseU0 + boff + sPubU, pubU, u0x, u0y, uz);
        pub_pred(baseU1 + boff + sPubU, pubU, u1x, u1y, uz);

        // intra-warp exchange (10 shuffles for 2 rows)
        float naX0s = __shfl_down_sync(FULLMASK, p0r, 1);
        float naY0s = __shfl_down_sync(FULLMASK, p0i, 1);
        float naX1s = __shfl_down_sync(FULLMASK, p1r, 1);
        float naY1s = __shfl_down_sync(FULLMASK, p1i, 1);
        float ux0s  = __shfl_up_sync(FULLMASK, u0x, 1);
        float uy0s  = __shfl_up_sync(FULLMASK, u0y, 1);
        float ux1s  = __shfl_up_sync(FULLMASK, u1x, 1);
        float uy1s  = __shfl_up_sync(FULLMASK, u1y, 1);
        float uzs   = __shfl_up_sync(FULLMASK, uz, 1);

        // ---- middle B MZI (c1,c2): thread-local, fills shfl latency ----
        {
            float pmr = tB0.x*q0r - tB0.y*q0i;
            float pmi = tB0.y*q0r + tB0.x*q0i;
            float n1r = tB0.z*pmr - tB0.w*r0i;
            float n1i = tB0.z*pmi + tB0.w*r0r;
            float n2r = tB0.z*r0r - tB0.w*pmi;
            float n2i = tB0.z*r0i + tB0.w*pmr;
            q0r = n1r; q0i = n1i; r0r = n2r; r0i = n2i;
        }
        {
            float pmr = tB0.x*q1r - tB0.y*q1i;
            float pmi = tB0.y*q1r + tB0.x*q1i;
            float n1r = tB0.z*pmr - tB0.w*r1i;
            float n1i = tB0.z*pmi + tB0.w*r1r;
            float n2r = tB0.z*r1r - tB0.w*pmi;
            float n2i = tB0.z*r1i + tB0.w*pmr;
            q1r = n1r; q1i = n1i; r1r = n2r; r1i = n2i;
        }

        __syncthreads();   // single CTA barrier per layer pair

        float4 sA0 = lds4(baseA0 + boff + sRdA);
        float4 sA1 = lds4(baseA1 + boff + sRdA);
        float4 sU0 = lds4(baseU0 + boff + sRdU);
        float4 sU1 = lds4(baseU1 + boff + sRdU);

        float naX0 = isL31 ? sA0.x : naX0s;   // t=255: tB1 identity -> harmless
        float naY0 = isL31 ? sA0.y : naY0s;
        float naX1 = isL31 ? sA1.x : naX1s;
        float naY1 = isL31 ? sA1.y : naY1s;
        float vx0 = isL0 ? sU0.x : ux0s;
        float vy0 = isL0 ? sU0.y : uy0s;
        float vx1 = isL0 ? sU1.x : ux1s;
        float vy1 = isL0 ? sU1.y : uy1s;
        float vz  = isL0 ? sU0.z : uzs;
        vx0 = isT0 ? 0.f : vx0;  vy0 = isT0 ? 0.f : vy0;
        vx1 = isT0 ? 0.f : vx1;  vy1 = isT0 ? 0.f : vy1;
        vz  = isT0 ? 1.f : vz;

        // c3' = a-output of edge MZI; c0' = b-output of left edge MZI (both rows)
        s0r = tB1.z*e0r - tB1.w*naY0;
        s0i = tB1.z*e0i + tB1.w*naX0;
        s1r = tB1.z*e1r - tB1.w*naY1;
        s1i = tB1.z*e1i + tB1.w*naX1;
        float np0r = vz*p0r - vy0;
        float np0i = vz*p0i + vx0;
        float np1r = vz*p1r - vy1;
        float np1i = vz*p1i + vx1;
        p0r = np0r; p0i = np0i; p1r = np1r; p1i = np1i;
    }

    // ---- epilogue (both rows) ----
    float4 bR4 = ((const float4*)bR)[t];
    float4 bI4 = ((const float4*)bI)[t];
    float4 om4 = ((const float4*)om)[t];
    float4 mb4 = ((const float4*)mb)[t];
    float co4[4], so4[4];
    {
        float oma[4] = {om4.x, om4.y, om4.z, om4.w};
        #pragma unroll
        for (int j = 0; j < 4; j++) sincosf(oma[j], &so4[j], &co4[j]);
    }
    float mba[4] = {mb4.x, mb4.y, mb4.z, mb4.w};
    float bRa[4] = {bR4.x, bR4.y, bR4.z, bR4.w};
    float bIa[4] = {bI4.x, bI4.y, bI4.z, bI4.w};

    #pragma unroll
    for (int rowsel = 0; rowsel < 2; rowsel++) {
        const int bb = rowsel ? b1v : b0v;
        float hr[4], hi[4];
        if (rowsel == 0) {
            hr[0]=p0r; hr[1]=q0r; hr[2]=r0r; hr[3]=s0r;
            hi[0]=p0i; hi[1]=q0i; hi[2]=r0i; hi[3]=s0i;
        } else {
            hr[0]=p1r; hr[1]=q1r; hr[2]=r1r; hr[3]=s1r;
            hi[0]=p1i; hi[1]=q1i; hi[2]=r1i; hi[3]=s1i;
        }
        float ihR[4] = {bRa[0], bRa[1], bRa[2], bRa[3]};
        float ihI[4] = {bIa[0], bIa[1], bIa[2], bIa[3]};
        #pragma unroll
        for (int c = 0; c < 4; c++) {
            float4 pr4 = *(const float4*)&g_pR[c][bb * HH + 4 * t];
            float4 pi4 = *(const float4*)&g_pI[c][bb * HH + 4 * t];
            ihR[0] += pr4.x; ihR[1] += pr4.y; ihR[2] += pr4.z; ihR[3] += pr4.w;
            ihI[0] += pi4.x; ihI[1] += pi4.y; ihI[2] += pi4.z; ihI[3] += pi4.w;
        }
        float zr[4], zi[4];
        #pragma unroll
        for (int j = 0; j < 4; j++) {
            float zrr = ihR[j] + co4[j]*hr[j] - so4[j]*hi[j];
            float zii = ihI[j] + so4[j]*hr[j] + co4[j]*hi[j];
            float mag = sqrtf(zrr*zrr + zii*zii);
            float sc  = fmaxf(mag + mba[j], 0.f) / fmaxf(mag, 1e-8f);
            zr[j] = sc*zrr; zi[j] = sc*zii;
        }
        ((float4*)(out + bb * HH))[t]           = make_float4(zr[0], zr[1], zr[2], zr[3]);
        ((float4*)(out + BB * HH + bb * HH))[t] = make_float4(zi[0], zi[1], zi[2], zi[3]);
    }
}

// ---------------------------------------------------------------------------
extern "C" void kernel_launch(void* const* d_in, const int* in_sizes, int n_in,
                              void* d_out, int out_size)
{
    const float* inR = (const float*)d_in[0];
    const float* inI = (const float*)d_in[1];
    const float* stR = (const float*)d_in[2];
    const float* stI = (const float*)d_in[3];
    const float* wR  = (const float*)d_in[4];
    const float* wI  = (const float*)d_in[5];
    const float* bR  = (const float*)d_in[6];
    const float* bI  = (const float*)d_in[7];
    const float* A0  = (const float*)d_in[8];
    const float* A1  = (const float*)d_in[9];
    const float* B0  = (const float*)d_in[10];
    const float* B1  = (const float*)d_in[11];
    const float* om  = (const float*)d_in[12];
    const float* mb  = (const float*)d_in[13];
    float* out = (float*)d_out;

    k1<<<256, 256>>>(inR, inI, wR, wI, A0, A1, B0, B1);
    k2<<<64, 256>>>(stR, stI, bR, bI, om, mb, out);
}

// round 12
// speedup vs baseline: 1.3890x; 1.3890x over previous
#include <cuda_runtime.h>
#include <cstdint>

// Problem constants
#define BB   128   // batch
#define INW  256   // input width
#define HH   1024  // hidden
#define NP   512   // pairs per A layer
#define LP   128   // number of (A,B) layer pairs
#define FULLMASK 0xffffffffu

// Per-warp-region trig tables (halo-duplicated, identity-padded):
// layout [layer][w][j][l] flat; offset = k*768 + w*96 + j*32 + l (float4 units)
// entry (w,j,l) = global pair g = 64w - 16 + 3l + j ; OOB -> identity (1,0,1,0)
__device__ float4 g_tA[(LP + 2) * 768];
__device__ float4 g_tB[(LP + 2) * 768];
__device__ float  g_pR[4][BB * HH];         // GEMM partials per K-chunk
__device__ float  g_pI[4][BB * HH];

// ---------------------------------------------------------------------------
// Kernel 1: blocks [0,128) = complex GEMM (K-split x4, N-tiles of 32)
//           blocks [128,256) = per-warp-region trig tables (one block/layer)
// ---------------------------------------------------------------------------
__global__ __launch_bounds__(256) void k1(
    const float* __restrict__ inR, const float* __restrict__ inI,
    const float* __restrict__ wR,  const float* __restrict__ wI,
    const float* __restrict__ A0,  const float* __restrict__ A1,
    const float* __restrict__ B0,  const float* __restrict__ B1)
{
    const int bid = blockIdx.x, tid = threadIdx.x;

    if (bid >= 128) {
        const int k = bid - 128;
        for (int i = tid; i < 768; i += 256) {
            const int w = i / 96, r = i % 96, j = r / 32, l = r % 32;
            const int g = 64 * w - 16 + 3 * l + j;
            float4 va = make_float4(1.f, 0.f, 1.f, 0.f);
            float4 vb = make_float4(1.f, 0.f, 1.f, 0.f);
            if (g >= 0 && g < 512) {
                float c0, s0, c1, s1;
                sincosf(A0[k * 512 + g], &s0, &c0);
                sincosf(A1[k * 512 + g], &s1, &c1);
                va = make_float4(c0, s0, c1, s1);
            }
            if (g >= 0 && g < 511) {
                float c0, s0, c1, s1;
                sincosf(B0[k * 511 + g], &s0, &c0);
                sincosf(B1[k * 511 + g], &s1, &c1);
                vb = make_float4(c0, s0, c1, s1);
            }
            g_tA[k * 768 + i] = va;
            g_tB[k * 768 + i] = vb;
        }
        return;
    }

    // ---- complex GEMM: tile M=128, N=32, K-chunk=64 ----
    const int kc = bid >> 5, nt = bid & 31;
    const int k0 = kc * 64, n0 = nt * 32;

    __shared__ float sXR[32][132], sXI[32][132];
    __shared__ float sWR[32][33],  sWI[32][33];

    float accR[8][2], accI[8][2];
    #pragma unroll
    for (int r = 0; r < 8; r++)
        #pragma unroll
        for (int c = 0; c < 2; c++) { accR[r][c] = 0.f; accI[r][c] = 0.f; }

    const int mi = tid >> 4, ni = tid & 15;
    const int lm = tid & 127, kh = (tid >> 7) * 16;
    const int wn = tid >> 3,  wk = (tid & 7) * 4;

    for (int ks = 0; ks < 64; ks += 32) {
        __syncthreads();
        #pragma unroll
        for (int j = 0; j < 4; j++) {
            const int kk = kh + j * 4;
            float4 vR = *(const float4*)(inR + lm * INW + k0 + ks + kk);
            float4 vI = *(const float4*)(inI + lm * INW + k0 + ks + kk);
            sXR[kk+0][lm] = vR.x; sXR[kk+1][lm] = vR.y;
            sXR[kk+2][lm] = vR.z; sXR[kk+3][lm] = vR.w;
            sXI[kk+0][lm] = vI.x; sXI[kk+1][lm] = vI.y;
            sXI[kk+2][lm] = vI.z; sXI[kk+3][lm] = vI.w;
        }
        {
            float4 vR = *(const float4*)(wR + (n0 + wn) * INW + k0 + ks + wk);
            float4 vI = *(const float4*)(wI + (n0 + wn) * INW + k0 + ks + wk);
            sWR[wk+0][wn] = vR.x; sWR[wk+1][wn] = vR.y;
            sWR[wk+2][wn] = vR.z; sWR[wk+3][wn] = vR.w;
            sWI[wk+0][wn] = vI.x; sWI[wk+1][wn] = vI.y;
            sWI[wk+2][wn] = vI.z; sWI[wk+3][wn] = vI.w;
        }
        __syncthreads();

        #pragma unroll 8
        for (int kk = 0; kk < 32; kk++) {
            float aRv[8], aIv[8], bRv[2], bIv[2];
            *(float4*)&aRv[0] = *(const float4*)&sXR[kk][mi * 8];
            *(float4*)&aRv[4] = *(const float4*)&sXR[kk][mi * 8 + 4];
            *(float4*)&aIv[0] = *(const float4*)&sXI[kk][mi * 8];
            *(float4*)&aIv[4] = *(const float4*)&sXI[kk][mi * 8 + 4];
            bRv[0] = sWR[kk][ni*2]; bRv[1] = sWR[kk][ni*2+1];
            bIv[0] = sWI[kk][ni*2]; bIv[1] = sWI[kk][ni*2+1];
            #pragma unroll
            for (int r = 0; r < 8; r++)
                #pragma unroll
                for (int c = 0; c < 2; c++) {
                    accR[r][c] += aRv[r]*bRv[c] - aIv[r]*bIv[c];
                    accI[r][c] += aRv[r]*bIv[c] + aIv[r]*bRv[c];
                }
        }
    }

    #pragma unroll
    for (int r = 0; r < 8; r++) {
        const int m = mi * 8 + r;
        #pragma unroll
        for (int c = 0; c < 2; c++) {
            g_pR[kc][m * HH + n0 + ni*2 + c] = accR[r][c];
            g_pI[kc][m * HH + n0 + ni*2 + c] = accI[r][c];
        }
    }
}

// ---------------------------------------------------------------------------
// helpers
// ---------------------------------------------------------------------------
__device__ __forceinline__ float4 ldg_v4_pinned(const float4* p) {
    float4 v;
    asm volatile("ld.global.nc.v4.f32 {%0,%1,%2,%3}, [%4];"
                 : "=f"(v.x), "=f"(v.y), "=f"(v.z), "=f"(v.w) : "l"(p));
    return v;
}

__device__ __forceinline__ void sts2_pred(uint32_t addr, int pred, float x, float y) {
    asm volatile("{\n\t"
                 ".reg .pred p;\n\t"
                 "setp.ne.s32 p, %0, 0;\n\t"
                 "@p st.shared.v2.f32 [%1], {%2,%3};\n\t"
                 "}"
                 :: "r"(pred), "r"(addr), "f"(x), "f"(y) : "memory");
}

// ---------------------------------------------------------------------------
// Kernel 2: Clements mesh — halo-decoupled warps.
// Warp w owns channels [128w,128w+128), works on 192 (halo 32/side, 6/lane).
// 16 layer pairs run shfl-only (no barriers, no smem); garbage creeps
// 2 ch/pair from warp edges, staying inside the halo. Every 16 pairs: one
// predicated owned-write to a double-buffered smem image + __syncthreads.
// ---------------------------------------------------------------------------
__global__ __launch_bounds__(256, 1) void k2(
    const float* __restrict__ stR, const float* __restrict__ stI,
    const float* __restrict__ bR,  const float* __restrict__ bI,
    const float* __restrict__ om,  const float* __restrict__ mb,
    float* __restrict__ out)
{
    const int b = blockIdx.x, t = threadIdx.x;
    const int w = t >> 5, l = t & 31;
    const int c = 128 * w - 32 + 6 * l;        // my 6 channels: c .. c+5

    __shared__ float2 simg[2][HH];             // double-buffered state image

    const uint32_t imgBase = (uint32_t)__cvta_generic_to_shared(simg);

    // initial state: read my 6 channels (clamped) from global
    float xr[6], xi[6];
    #pragma unroll
    for (int j = 0; j < 6; j++) {
        int gc = c + j; gc = gc < 0 ? 0 : (gc > HH - 1 ? HH - 1 : gc);
        xr[j] = stR[b * HH + gc];
        xi[j] = stI[b * HH + gc];
    }

    const int idx0 = w * 96 + l;               // table offset within layer
    const float4* gA = g_tA;
    const float4* gB = g_tB;

    // current trig (layer 0) + running prefetch offset (layer 1)
    float4 cA0 = ldg_v4_pinned(gA + idx0);
    float4 cA1 = ldg_v4_pinned(gA + idx0 + 32);
    float4 cA2 = ldg_v4_pinned(gA + idx0 + 64);
    float4 cB0 = ldg_v4_pinned(gB + idx0);
    float4 cB1 = ldg_v4_pinned(gB + idx0 + 32);
    float4 cB2 = ldg_v4_pinned(gB + idx0 + 64);
    int off = 768 + idx0;

    const int ownPred6[1] = {0}; (void)ownPred6;

    for (int e = 0; e < 8; e++) {
        #pragma unroll
        for (int kk = 0; kk < 16; kk++) {
            // prefetch next layer pair's trig (depth-1)
            float4 nA0 = ldg_v4_pinned(gA + off);
            float4 nA1 = ldg_v4_pinned(gA + off + 32);
            float4 nA2 = ldg_v4_pinned(gA + off + 64);
            float4 nB0 = ldg_v4_pinned(gB + off);
            float4 nB1 = ldg_v4_pinned(gB + off + 32);
            float4 nB2 = ldg_v4_pinned(gB + off + 64);
            off += 768;

            // ---- layer A: 3 lane-local MZIs (x0,x1)(x2,x3)(x4,x5) ----
            {
                float pr = cA0.x*xr[0] - cA0.y*xi[0];
                float pi = cA0.y*xr[0] + cA0.x*xi[0];
                float a = cA0.z*pr - cA0.w*xi[1];
                float bq = cA0.z*pi + cA0.w*xr[1];
                float d = cA0.z*xr[1] - cA0.w*pi;
                float f = cA0.z*xi[1] + cA0.w*pr;
                xr[0] = a; xi[0] = bq; xr[1] = d; xi[1] = f;
            }
            {
                float pr = cA1.x*xr[2] - cA1.y*xi[2];
                float pi = cA1.y*xr[2] + cA1.x*xi[2];
                float a = cA1.z*pr - cA1.w*xi[3];
                float bq = cA1.z*pi + cA1.w*xr[3];
                float d = cA1.z*xr[3] - cA1.w*pi;
                float f = cA1.z*xi[3] + cA1.w*pr;
                xr[2] = a; xi[2] = bq; xr[3] = d; xi[3] = f;
            }
            {
                float pr = cA2.x*xr[4] - cA2.y*xi[4];
                float pi = cA2.y*xr[4] + cA2.x*xi[4];
                float a = cA2.z*pr - cA2.w*xi[5];
                float bq = cA2.z*pi + cA2.w*xr[5];
                float d = cA2.z*xr[5] - cA2.w*pi;
                float f = cA2.z*xi[5] + cA2.w*pr;
                xr[4] = a; xi[4] = bq; xr[5] = d; xi[5] = f;
            }

            // ---- edge B MZI (x5, right neighbor's x0): phase + u ----
            float p5r = cB2.x*xr[5] - cB2.y*xi[5];
            float p5i = cB2.y*xr[5] + cB2.x*xi[5];
            float ux = cB2.w*p5r, uy = cB2.w*p5i, uz = cB2.z;

            // intra-warp exchange (warp-edge lanes get self = halo garbage)
            float nb0r = __shfl_down_sync(FULLMASK, xr[0], 1);
            float nb0i = __shfl_down_sync(FULLMASK, xi[0], 1);
            float lux = __shfl_up_sync(FULLMASK, ux, 1);
            float luy = __shfl_up_sync(FULLMASK, uy, 1);
            float luz = __shfl_up_sync(FULLMASK, uz, 1);

            // ---- 2 mid B MZIs (x1,x2)(x3,x4): lane-local, fill shfl latency ----
            {
                float pmr = cB0.x*xr[1] - cB0.y*xi[1];
                float pmi = cB0.y*xr[1] + cB0.x*xi[1];
                float a = cB0.z*pmr - cB0.w*xi[2];
                float bq = cB0.z*pmi + cB0.w*xr[2];
                float d = cB0.z*xr[2] - cB0.w*pmi;
                float f = cB0.z*xi[2] + cB0.w*pmr;
                xr[1] = a; xi[1] = bq; xr[2] = d; xi[2] = f;
            }
            {
                float pmr = cB1.x*xr[3] - cB1.y*xi[3];
                float pmi = cB1.y*xr[3] + cB1.x*xi[3];
                float a = cB1.z*pmr - cB1.w*xi[4];
                float bq = cB1.z*pmi + cB1.w*xr[4];
                float d = cB1.z*xr[4] - cB1.w*pmi;
                float f = cB1.z*xi[4] + cB1.w*pmr;
                xr[3] = a; xi[3] = bq; xr[4] = d; xi[4] = f;
            }

            // ---- completions: my x5 (right edge), my x0 (left edge) ----
            {
                float a = cB2.z*p5r - cB2.w*nb0i;
                float bq = cB2.z*p5i + cB2.w*nb0r;
                xr[5] = a; xi[5] = bq;
            }
            {
                float a = luz*xr[0] - luy;
                float bq = luz*xi[0] + lux;
                xr[0] = a; xi[0] = bq;
            }

            cA0 = nA0; cA1 = nA1; cA2 = nA2;
            cB0 = nB0; cB1 = nB1; cB2 = nB2;
        }

        // ---- sync: publish owned channels, barrier, refresh halo ----
        const uint32_t ib = imgBase + (uint32_t)((e & 1) * HH * 8);
        #pragma unroll
        for (int j = 0; j < 6; j++) {
            const int g = c + j;
            const int pred = ((unsigned)(g - 128 * w) < 128u) ? 1 : 0;
            sts2_pred(ib + (uint32_t)(g * 8), pred, xr[j], xi[j]);
        }
        __syncthreads();
        if (e < 7) {
            #pragma unroll
            for (int j = 0; j < 6; j++) {
                int gc = c + j; gc = gc < 0 ? 0 : (gc > HH - 1 ? HH - 1 : gc);
                float2 v = simg[e & 1][gc];
                xr[j] = v.x; xi[j] = v.y;
            }
        }
    }

    // ---- epilogue: thread t handles channels 4t..4t+3 from image buf 1 ----
    float hr[4], hi[4];
    #pragma unroll
    for (int j = 0; j < 4; j++) {
        float2 v = simg[1][4 * t + j];
        hr[j] = v.x; hi[j] = v.y;
    }

    float4 bR4 = ((const float4*)bR)[t];
    float4 bI4 = ((const float4*)bI)[t];
    float ihR[4] = {bR4.x, bR4.y, bR4.z, bR4.w};
    float ihI[4] = {bI4.x, bI4.y, bI4.z, bI4.w};
    #pragma unroll
    for (int cc = 0; cc < 4; cc++) {
        float4 pr4 = *(const float4*)&g_pR[cc][b * HH + 4 * t];
        float4 pi4 = *(const float4*)&g_pI[cc][b * HH + 4 * t];
        ihR[0] += pr4.x; ihR[1] += pr4.y; ihR[2] += pr4.z; ihR[3] += pr4.w;
        ihI[0] += pi4.x; ihI[1] += pi4.y; ihI[2] += pi4.z; ihI[3] += pi4.w;
    }
    float4 om4 = ((const float4*)om)[t];
    float4 mb4 = ((const float4*)mb)[t];
    float oma[4] = {om4.x, om4.y, om4.z, om4.w};
    float mba[4] = {mb4.x, mb4.y, mb4.z, mb4.w};

    float zr[4], zi[4];
    #pragma unroll
    for (int j = 0; j < 4; j++) {
        float co, so;
        sincosf(oma[j], &so, &co);
        float zrr = ihR[j] + co*hr[j] - so*hi[j];
        float zii = ihI[j] + so*hr[j] + co*hi[j];
        float mag = sqrtf(zrr*zrr + zii*zii);
        float sc  = fmaxf(mag + mba[j], 0.f) / fmaxf(mag, 1e-8f);
        zr[j] = sc*zrr; zi[j] = sc*zii;
    }
    ((float4*)(out + b * HH))[t]           = make_float4(zr[0], zr[1], zr[2], zr[3]);
    ((float4*)(out + BB * HH + b * HH))[t] = make_float4(zi[0], zi[1], zi[2], zi[3]);
}

// ---------------------------------------------------------------------------
extern "C" void kernel_launch(void* const* d_in, const int* in_sizes, int n_in,
                              void* d_out, int out_size)
{
    const float* inR = (const float*)d_in[0];
    const float* inI = (const float*)d_in[1];
    const float* stR = (const float*)d_in[2];
    const float* stI = (const float*)d_in[3];
    const float* wR  = (const float*)d_in[4];
    const float* wI  = (const float*)d_in[5];
    const float* bR  = (const float*)d_in[6];
    const float* bI  = (const float*)d_in[7];
    const float* A0  = (const float*)d_in[8];
    const float* A1  = (const float*)d_in[9];
    const float* B0  = (const float*)d_in[10];
    const float* B1  = (const float*)d_in[11];
    const float* om  = (const float*)d_in[12];
    const float* mb  = (const float*)d_in[13];
    float* out = (float*)d_out;

    k1<<<256, 256>>>(inR, inI, wR, wI, A0, A1, B0, B1);
    k2<<<128, 256>>>(stR, stI, bR, bI, om, mb, out);
}